// round 4
// baseline (speedup 1.0000x reference)
#include <cuda_runtime.h>
#include <cstdint>

#define NQ 32768
#define RELW 36
#define EPAD 68          // smem row stride in floats (16B-aligned, bank-skewed)

// rel scratch: [q][36] = relH[0..15], relW[16..31], relT[32..35]
__device__ float g_rel[NQ * RELW];

__device__ __forceinline__ void fma2(unsigned long long& d,
                                     unsigned long long a,
                                     unsigned long long b) {
    asm("fma.rn.f32x2 %0, %1, %2, %0;" : "+l"(d) : "l"(a), "l"(b));
}

// ---------------------------------------------------------------------------
// Kernel 1: rel GEMM.  P = Q[64 queries] @ Ecat^T[69 cols], Ecat = [H(31)|W(31)|T(7)].
// Block: 128 threads, Mtile=64.  Thread tile 4q x 9col, f32x2 packed FMA.
// Epilogue scatters valid (q,col) products straight into g_rel[q][36].
// ---------------------------------------------------------------------------
__global__ __launch_bounds__(128)
void rel_gemm(const float* __restrict__ query,
              const float* __restrict__ Hemb,   // [31,64]
              const float* __restrict__ Wemb,   // [31,64]
              const float* __restrict__ Temb)   // [7,64]
{
    __shared__ float sQ[64 * EPAD];   // 17.4 KB
    __shared__ float sE[72 * EPAD];   // 19.6 KB (cols 69..71 zero)

    const int tid   = threadIdx.x;
    const int qbase = blockIdx.x * 64;

    // stage Q tile (64*64 floats, contiguous)
    const float* qsrc = query + (size_t)qbase * 64;
    for (int i = tid; i < 64 * 64; i += 128)
        sQ[(i >> 6) * EPAD + (i & 63)] = qsrc[i];

    // stage Ecat (69 rows + 3 zero rows)
    for (int i = tid; i < 72 * 64; i += 128) {
        int r = i >> 6, c = i & 63;
        float v = 0.f;
        if (r < 31)      v = Hemb[r * 64 + c];
        else if (r < 62) v = Wemb[(r - 31) * 64 + c];
        else if (r < 69) v = Temb[(r - 62) * 64 + c];
        sE[r * EPAD + c] = v;
    }
    __syncthreads();

    const int tq = tid >> 3;   // 0..15 -> queries tq*4 .. tq*4+3
    const int tr = tid & 7;    // 0..7  -> cols tr*9 .. tr*9+8

    unsigned long long acc[4][9];
    #pragma unroll
    for (int i = 0; i < 4; i++)
        #pragma unroll
        for (int j = 0; j < 9; j++) acc[i][j] = 0ull;   // packed (0.f,0.f)

    #pragma unroll
    for (int k4 = 0; k4 < 16; k4++) {
        ulonglong2 qv[4], ev[9];
        #pragma unroll
        for (int i = 0; i < 4; i++)
            qv[i] = *reinterpret_cast<const ulonglong2*>(&sQ[(tq * 4 + i) * EPAD + k4 * 4]);
        #pragma unroll
        for (int j = 0; j < 9; j++)
            ev[j] = *reinterpret_cast<const ulonglong2*>(&sE[(tr * 9 + j) * EPAD + k4 * 4]);
        #pragma unroll
        for (int i = 0; i < 4; i++)
            #pragma unroll
            for (int j = 0; j < 9; j++) {
                fma2(acc[i][j], qv[i].x, ev[j].x);
                fma2(acc[i][j], qv[i].y, ev[j].y);
            }
    }

    // epilogue: horizontal add + scatter into g_rel
    #pragma unroll
    for (int i = 0; i < 4; i++) {
        const int q = qbase + tq * 4 + i;
        const int w = q & 15;
        const int h = (q >> 4) & 15;
        const int t = (q >> 8) & 3;
        float* dst = g_rel + (size_t)q * RELW;
        #pragma unroll
        for (int j = 0; j < 9; j++) {
            const int c = tr * 9 + j;
            unsigned long long a = acc[i][j];
            float s = __uint_as_float((unsigned)a) + __uint_as_float((unsigned)(a >> 32));
            if (c < 31) {                       // H section: col = h + 15 - kh
                int kh = h + 15 - c;
                if (kh >= 0 && kh < 16) dst[kh] = s;
            } else if (c < 62) {                // W section: col-31 = w + 15 - kw
                int kw = w + 15 - (c - 31);
                if (kw >= 0 && kw < 16) dst[16 + kw] = s;
            } else if (c < 69) {                // T section: col-62 = t + 3 - kt
                int kt = t + 3 - (c - 62);
                if (kt >= 0 && kt < 4) dst[32 + kt] = s;
            }
        }
    }
}

// ---------------------------------------------------------------------------
// Kernel 2: pure stream (unchanged from R2: 38.8us @ 71.9% DRAM).
// ---------------------------------------------------------------------------
#define QW 16
#define SRS 40   // smem rel row stride (16B-aligned)

__global__ __launch_bounds__(256)
void stream_kernel(const float* __restrict__ scores,
                   float* __restrict__ out)
{
    __shared__ float sRel[QW][SRS];

    const int bid = blockIdx.x;
    const int tid = threadIdx.x;
    const int qbase = (bid >> 6) * 1024 + ((bid >> 4) & 3) * 256 + (bid & 15) * 16;

    const float* relsrc = g_rel + (size_t)qbase * RELW;
    for (int i = tid; i < QW * RELW; i += 256) {
        int w = i / RELW;
        sRel[w][i - w * RELW] = relsrc[i];
    }
    __syncthreads();

    const int kt  = tid >> 6;
    const int kh  = (tid >> 2) & 15;
    const int kw4 = (tid & 3) << 2;

    const size_t rowbase = (size_t)qbase * 1024;
    const float4* sc4 = (const float4*)(scores + rowbase);
    float4*       ot4 = (float4*)(out + rowbase);

    #pragma unroll 8
    for (int w = 0; w < QW; w++) {
        int v = (w << 8) + tid;
        float4 s = sc4[v];
        float base = sRel[w][kh] + sRel[w][32 + kt];
        float4 rw = *(const float4*)&sRel[w][16 + kw4];
        s.x += base + rw.x;
        s.y += base + rw.y;
        s.z += base + rw.z;
        s.w += base + rw.w;
        ot4[v] = s;
    }
}

extern "C" void kernel_launch(void* const* d_in, const int* in_sizes, int n_in,
                              void* d_out, int out_size) {
    const float* query  = (const float*)d_in[0];
    const float* scores = (const float*)d_in[1];
    const float* Hemb   = (const float*)d_in[2];
    const float* Wemb   = (const float*)d_in[3];
    const float* Temb   = (const float*)d_in[4];
    float* out = (float*)d_out;

    rel_gemm<<<512, 128>>>(query, Hemb, Wemb, Temb);
    stream_kernel<<<2048, 256>>>(scores, out);
}

// round 5
// speedup vs baseline: 1.3235x; 1.3235x over previous
#include <cuda_runtime.h>
#include <cstdint>

#define NQ 32768
#define RELW 36

typedef unsigned long long ull;

// rel scratch: [q][36] = relH[0..15], relW[16..31], relT[32..35]
__device__ float g_rel[NQ * RELW];

__device__ __forceinline__ void fma2(ull& d, ull a, ull b) {
    asm("fma.rn.f32x2 %0, %1, %2, %0;" : "+l"(d) : "l"(a), "l"(b));
}

// ---------------------------------------------------------------------------
// Kernel 1: rel GEMM.  P[128q x 72c] = Q @ Ecat^T, Ecat = [H(31)|W(31)|T(7)|0(3)].
// Block: 288 threads (9 warps). Warp w owns cols w*8..w*8+7 (ev loads are
// warp-broadcast). Lane l owns queries {l, l+32, l+64, l+96} (qv loads hit
// 32 consecutive 8B words -> conflict-free). k packed in f32x2 pairs.
// ---------------------------------------------------------------------------
#define QP 129   // sQp row stride in ull (odd -> staging STS conflict-free)
#define EP 73    // sEp row stride in ull
#define RELSMEM ((32 * QP + 32 * EP) * 8)   // 51,712 B dynamic smem

__global__ __launch_bounds__(288)
void rel_gemm(const float* __restrict__ query,
              const float* __restrict__ Hemb,   // [31,64]
              const float* __restrict__ Wemb,   // [31,64]
              const float* __restrict__ Temb)   // [7,64]
{
    extern __shared__ ull smem[];
    ull* sQp = smem;            // [32][QP]  sQp[kk][q] = (q, 2kk..2kk+1)
    ull* sEp = smem + 32 * QP;  // [32][EP]  sEp[kk][c]

    const int tid   = threadIdx.x;
    const int qbase = blockIdx.x * 128;

    // stage Q tile transposed to k-major packed pairs (coalesced 8B gmem loads)
    const ull* qsrc = (const ull*)(query + (size_t)qbase * 64);
    for (int i = tid; i < 128 * 32; i += 288) {
        int q = i >> 5, kk = i & 31;
        sQp[kk * QP + q] = qsrc[i];
    }
    // stage Ecat (72 cols: H 0..30, W 31..61, T 62..68, zero 69..71)
    for (int i = tid; i < 72 * 32; i += 288) {
        int c = i >> 5, kk = i & 31;
        ull v = 0ull;
        if (c < 31)      v = ((const ull*)Hemb)[c * 32 + kk];
        else if (c < 62) v = ((const ull*)Wemb)[(c - 31) * 32 + kk];
        else if (c < 69) v = ((const ull*)Temb)[(c - 62) * 32 + kk];
        sEp[kk * EP + c] = v;
    }
    __syncthreads();

    const int tq = tid & 31;    // lane -> queries tq + 32*i
    const int tc = tid >> 5;    // warp -> cols tc*8 .. tc*8+7

    ull acc[4][8];
    #pragma unroll
    for (int i = 0; i < 4; i++)
        #pragma unroll
        for (int j = 0; j < 8; j++) acc[i][j] = 0ull;

    #pragma unroll 4
    for (int kk = 0; kk < 32; kk++) {
        ull qv[4], ev[8];
        #pragma unroll
        for (int i = 0; i < 4; i++) qv[i] = sQp[kk * QP + tq + 32 * i];
        #pragma unroll
        for (int j = 0; j < 8; j++) ev[j] = sEp[kk * EP + tc * 8 + j];
        #pragma unroll
        for (int i = 0; i < 4; i++)
            #pragma unroll
            for (int j = 0; j < 8; j++) fma2(acc[i][j], qv[i], ev[j]);
    }

    // epilogue: horizontal add + scatter into g_rel[q][36]
    #pragma unroll
    for (int i = 0; i < 4; i++) {
        const int q = qbase + tq + 32 * i;
        const int w = q & 15;
        const int h = (q >> 4) & 15;
        const int t = (q >> 8) & 3;
        float* dst = g_rel + (size_t)q * RELW;
        #pragma unroll
        for (int j = 0; j < 8; j++) {
            const int c = tc * 8 + j;
            ull a = acc[i][j];
            float s = __uint_as_float((unsigned)a) + __uint_as_float((unsigned)(a >> 32));
            if (c < 31) {                       // H: col = h + 15 - kh
                int kh = h + 15 - c;
                if (kh >= 0 && kh < 16) dst[kh] = s;
            } else if (c < 62) {                // W: col-31 = w + 15 - kw
                int kw = w + 15 - (c - 31);
                if (kw >= 0 && kw < 16) dst[16 + kw] = s;
            } else if (c < 69) {                // T: col-62 = t + 3 - kt
                int kt = t + 3 - (c - 62);
                if (kt >= 0 && kt < 4) dst[32 + kt] = s;
            }
        }
    }
}

// ---------------------------------------------------------------------------
// Kernel 2: pure stream (R2 structure, + streaming cache hints).
// ---------------------------------------------------------------------------
#define QW 16
#define SRS 40   // smem rel row stride (16B-aligned)

__global__ __launch_bounds__(256)
void stream_kernel(const float* __restrict__ scores,
                   float* __restrict__ out)
{
    __shared__ float sRel[QW][SRS];

    const int bid = blockIdx.x;
    const int tid = threadIdx.x;
    const int qbase = (bid >> 6) * 1024 + ((bid >> 4) & 3) * 256 + (bid & 15) * 16;

    const float* relsrc = g_rel + (size_t)qbase * RELW;
    for (int i = tid; i < QW * RELW; i += 256) {
        int w = i / RELW;
        sRel[w][i - w * RELW] = relsrc[i];
    }
    __syncthreads();

    const int kt  = tid >> 6;
    const int kh  = (tid >> 2) & 15;
    const int kw4 = (tid & 3) << 2;

    const size_t rowbase = (size_t)qbase * 1024;
    const float4* sc4 = (const float4*)(scores + rowbase);
    float4*       ot4 = (float4*)(out + rowbase);

    #pragma unroll 8
    for (int w = 0; w < QW; w++) {
        int v = (w << 8) + tid;
        float4 s = __ldcs(&sc4[v]);
        float base = sRel[w][kh] + sRel[w][32 + kt];
        float4 rw = *(const float4*)&sRel[w][16 + kw4];
        s.x += base + rw.x;
        s.y += base + rw.y;
        s.z += base + rw.z;
        s.w += base + rw.w;
        __stcs(&ot4[v], s);
    }
}

extern "C" void kernel_launch(void* const* d_in, const int* in_sizes, int n_in,
                              void* d_out, int out_size) {
    const float* query  = (const float*)d_in[0];
    const float* scores = (const float*)d_in[1];
    const float* Hemb   = (const float*)d_in[2];
    const float* Wemb   = (const float*)d_in[3];
    const float* Temb   = (const float*)d_in[4];
    float* out = (float*)d_out;

    cudaFuncSetAttribute(rel_gemm, cudaFuncAttributeMaxDynamicSharedMemorySize, RELSMEM);
    rel_gemm<<<256, 288, RELSMEM>>>(query, Hemb, Wemb, Temb);
    stream_kernel<<<2048, 256>>>(scores, out);
}